// round 9
// baseline (speedup 1.0000x reference)
#include <cuda_runtime.h>
#include <cstdint>

// x: (8,16,2000,128) fp32. Per (b,c,f) column: POOL=10 block sums, causal
// cumulative mean/var over pooled blocks, normalize. Single pass.
//
// Grid = 512 CTAs: (b*C+c) x (f-quarter, QF=32 -> full 128B lines everywhere).
// 256 threads/CTA (~28 warps/SM). Ring of NS=4 tiles (TB=8 blocks x 10 x 32 =
// 10240 B). Per tile: each thread owns one (block,f) pair -> reads its 10
// elements ONCE into registers (tile never re-read), warp 0 runs the 8-step
// scan WHILE warps 1-7 issue the refill cp.asyncs, then all threads normalize
// from registers and store full-line STG.32.

#define TT      2000
#define FF      128
#define PP      10
#define TT1     200
#define TB      8                    // pooled blocks per tile
#define NT      25                   // tiles
#define NS      4                    // ring stages
#define QF      32                   // f-columns per CTA
#define ROWS    (TB * PP)            // 80 rows per tile
#define TILE_F  (ROWS * QF)          // 2560 floats
#define TILE_B  (TILE_F * 4)         // 10240 bytes
#define SLOTS4  (TILE_F / 4)         // 640 float4 slots
#define ROW_B   (FF * 4)             // 512-byte global row stride
#define EPSV    1e-5f

__device__ __forceinline__ uint32_t s2u32(const void* p) {
    uint32_t a;
    asm("{ .reg .u64 t; cvta.to.shared.u64 t, %1; cvt.u32.u64 %0, t; }"
        : "=r"(a) : "l"(p));
    return a;
}
__device__ __forceinline__ void cp16(uint32_t saddr, const void* gaddr) {
    asm volatile("cp.async.cg.shared.global [%0], [%1], 16;\n"
                 :: "r"(saddr), "l"(gaddr));
}
#define CP_COMMIT() asm volatile("cp.async.commit_group;\n")
#define CP_WAIT(n)  asm volatile("cp.async.wait_group %0;\n" :: "n"(n))

__global__ void __launch_bounds__(256)
inorm_kernel(const float* __restrict__ x, float* __restrict__ out)
{
    __shared__ float  ring[NS * TILE_F];        // 40960 B
    __shared__ float2 bsArr[TB * QF];           //  2048 B
    __shared__ float  mArr[TB * QF];            //  1024 B
    __shared__ float  rArr[TB * QF];            //  1024 B

    const int col = blockIdx.x >> 2;            // 0..127
    const int q   = blockIdx.x & 3;             // f-quarter
    const int tid = threadIdx.x;
    const int b   = tid >> 5;                   // block within tile, 0..7
    const int f   = tid & 31;                   // f within quarter

    const char* gq = (const char*)(x   + (size_t)col * (TT * FF) + q * QF);
    char*       oq = (char*)(out + (size_t)col * (TT * FF) + q * QF);

    const uint32_t sring = s2u32(ring);

    // Prologue: fill ring with tiles 0..NS-1 (one commit group per stage/warp)
    #pragma unroll
    for (int st = 0; st < NS; st++) {
        #pragma unroll
        for (int i = 0; i < 3; i++) {
            const int j = tid + 256 * i;        // float4 slot, 0..639
            if (j < SLOTS4) {
                const int r  = j >> 3;          // row 0..79
                const int c4 = j & 7;           // float4 within 128B row
                cp16(sring + st * TILE_B + j * 16,
                     gq + (size_t)(st * ROWS + r) * ROW_B + c4 * 16);
            }
        }
        CP_COMMIT();
    }

    float sAcc = 0.f, s2Acc = 0.f;              // live in warp 0 (lane = f)
    int st = 0;

    #pragma unroll 1
    for (int t = 0; t < NT; t++) {
        CP_WAIT(NS - 1);
        __syncthreads();          // all warps see stage st filled

        const float* tile = ring + st * TILE_F;

        // ── A: one thread per (b,f): read 10 elements ONCE into registers
        float a[PP];
        {
            const float* rp = tile + b * (PP * QF) + f;
            #pragma unroll
            for (int i = 0; i < PP; i++) a[i] = rp[i * QF];
        }
        float bs = 0.f, bs2 = 0.f;
        #pragma unroll
        for (int i = 0; i < PP; i++) { bs += a[i]; bs2 = fmaf(a[i], a[i], bs2); }
        bsArr[b * QF + f] = make_float2(bs, bs2);
        __syncthreads();          // bsArr ready; stage st fully consumed

        // ── B (warp 0): 8-step serial scan -> mArr/rArr
        //    (warps 1-7 concurrently): issue refill of stage st with tile t+NS
        if (tid < 32) {
            #pragma unroll
            for (int bb = 0; bb < TB; bb++) {
                const float2 v = bsArr[bb * QF + tid];
                sAcc += v.x; s2Acc += v.y;
                const float invn = __fdividef(1.0f, (float)((t * TB + bb + 1) * PP));
                const float m    = sAcc * invn;
                const float var  = fmaf(-m, m, s2Acc * invn);
                mArr[bb * QF + tid] = m;
                rArr[bb * QF + tid] = rsqrtf(var + EPSV);
            }
        } else {
            const int tn = t + NS;
            if (tn < NT) {
                const int tt = tid - 32;        // 0..223
                #pragma unroll
                for (int i = 0; i < 3; i++) {
                    const int j = tt + 224 * i; // 0..671 -> guard at 640
                    if (j < SLOTS4) {
                        const int r  = j >> 3;
                        const int c4 = j & 7;
                        cp16(sring + st * TILE_B + j * 16,
                             gq + (size_t)(tn * ROWS + r) * ROW_B + c4 * 16);
                    }
                }
            }
        }
        CP_COMMIT();              // every warp commits every iteration
        __syncthreads();          // mArr/rArr visible to all

        // ── C: normalize from registers, full-line STG.32
        {
            const float m = mArr[b * QF + f];
            const float r = rArr[b * QF + f];
            char* og = oq + (size_t)(t * ROWS + b * PP) * ROW_B + f * 4;
            #pragma unroll
            for (int i = 0; i < PP; i++)
                *(float*)(og + (size_t)i * ROW_B) = (a[i] - m) * r;
        }

        if (++st == NS) st = 0;
    }
}

extern "C" void kernel_launch(void* const* d_in, const int* in_sizes, int n_in,
                              void* d_out, int out_size)
{
    const float* x   = (const float*)d_in[0];
    float*       out = (float*)d_out;
    inorm_kernel<<<512, 256>>>(x, out);
}

// round 10
// speedup vs baseline: 1.0096x; 1.0096x over previous
#include <cuda_runtime.h>
#include <cstdint>

// x: (8,16,2000,128) fp32. Per (b,c,f) column: POOL=10 block sums, causal
// cumulative mean/var over pooled blocks, normalize. Single pass.
//
// Grid = 512 CTAs: (b*C+c) x (f-quarter QF=32, full 128B lines). 256 threads.
// Ring of NS=5 tiles (TB=8 blocks x 10 x 32 = 10240 B). Per tile (2 barriers):
//   A: thread (b,f) loads its 10 elements once into registers, writes block
//      sums to bsArr.
//   B: DISTRIBUTED scan — warp b redundantly sums bsArr[0..b] + ping-pong
//      carry, computes (m, rstd) in registers (no single-warp serial phase,
//      no m/r smem roundtrip). Warp 7 publishes the next carry.
//   C: normalize from registers, streaming STG (__stcs); all warps issue the
//      stage refill cp.asyncs.

#define TT      2000
#define FF      128
#define PP      10
#define TT1     200
#define TB      8
#define NT      25
#define NS      5
#define QF      32
#define ROWS    (TB * PP)            // 80
#define TILE_F  (ROWS * QF)          // 2560 floats
#define TILE_B  (TILE_F * 4)         // 10240 B
#define SLOTS4  (TILE_F / 4)         // 640 float4 slots
#define ROW_B   (FF * 4)             // 512 B global row stride
#define EPSV    1e-5f

__device__ __forceinline__ uint32_t s2u32(const void* p) {
    uint32_t a;
    asm("{ .reg .u64 t; cvta.to.shared.u64 t, %1; cvt.u32.u64 %0, t; }"
        : "=r"(a) : "l"(p));
    return a;
}
__device__ __forceinline__ void cp16(uint32_t saddr, const void* gaddr) {
    asm volatile("cp.async.cg.shared.global [%0], [%1], 16;\n"
                 :: "r"(saddr), "l"(gaddr));
}
#define CP_COMMIT() asm volatile("cp.async.commit_group;\n")
#define CP_WAIT(n)  asm volatile("cp.async.wait_group %0;\n" :: "n"(n))

__global__ void __launch_bounds__(256)
inorm_kernel(const float* __restrict__ x, float* __restrict__ out)
{
    __shared__ float  ring[NS * TILE_F];        // 51200 B
    __shared__ float2 bsArr[TB * QF];           //  2048 B
    __shared__ float2 carry[2][QF];             //   512 B

    const int col = blockIdx.x >> 2;            // 0..127
    const int q   = blockIdx.x & 3;             // f-quarter
    const int tid = threadIdx.x;
    const int b   = tid >> 5;                   // warp = block in tile, 0..7
    const int f   = tid & 31;                   // lane = f within quarter

    const char* gq = (const char*)(x   + (size_t)col * (TT * FF) + q * QF);
    char*       oq = (char*)(out + (size_t)col * (TT * FF) + q * QF);

    const uint32_t sring = s2u32(ring);

    if (tid < QF) {                             // zero carry slot 0
        carry[0][tid] = make_float2(0.f, 0.f);
    }

    // Prologue: fill ring with tiles 0..NS-1 (one commit group per stage)
    #pragma unroll
    for (int st = 0; st < NS; st++) {
        #pragma unroll
        for (int i = 0; i < 3; i++) {
            const int j = tid + 256 * i;        // float4 slot 0..639
            if (j < SLOTS4) {
                const int r  = j >> 3;
                const int c4 = j & 7;
                cp16(sring + st * TILE_B + j * 16,
                     gq + (size_t)(st * ROWS + r) * ROW_B + c4 * 16);
            }
        }
        CP_COMMIT();
    }

    int st = 0;

    #pragma unroll 1
    for (int t = 0; t < NT; t++) {
        CP_WAIT(NS - 1);
        __syncthreads();          // stage st ready; carry[t&1] published;
                                  // previous tile's bsArr reads finished

        const float* tile = ring + st * TILE_F;

        // ── A: load my (b,f) block once into registers; exchange block sums
        float a[PP];
        {
            const float* rp = tile + b * (PP * QF) + f;
            #pragma unroll
            for (int i = 0; i < PP; i++) a[i] = rp[i * QF];
        }
        float bs = 0.f, bs2 = 0.f;
        #pragma unroll
        for (int i = 0; i < PP; i++) { bs += a[i]; bs2 = fmaf(a[i], a[i], bs2); }
        bsArr[b * QF + f] = make_float2(bs, bs2);
        __syncthreads();          // bsArr ready; stage st consumed to regs

        // ── B: distributed scan. warp b sums bsArr[0..b] + carry.
        float sA, s2A;
        {
            const float2 c0 = carry[t & 1][f];
            sA = c0.x; s2A = c0.y;
            #pragma unroll
            for (int j = 0; j < TB; j++) {
                if (j <= b) {                  // uniform per warp
                    const float2 v = bsArr[j * QF + f];
                    sA += v.x; s2A += v.y;
                }
            }
            if (b == TB - 1)                   // warp 7 publishes next carry
                carry[(t + 1) & 1][f] = make_float2(sA, s2A);
        }
        const float invn = __fdividef(1.0f, (float)((t * TB + b + 1) * PP));
        const float m    = sA * invn;
        const float var  = fmaf(-m, m, s2A * invn);
        const float r    = rsqrtf(var + EPSV);

        // ── C: normalize from registers, streaming stores
        {
            char* og = oq + (size_t)(t * ROWS + b * PP) * ROW_B + f * 4;
            #pragma unroll
            for (int i = 0; i < PP; i++)
                __stcs((float*)(og + (size_t)i * ROW_B), (a[i] - m) * r);
        }

        // ── refill stage st with tile t+NS (all warps; always commit)
        const int tn = t + NS;
        if (tn < NT) {
            #pragma unroll
            for (int i = 0; i < 3; i++) {
                const int j = tid + 256 * i;
                if (j < SLOTS4) {
                    const int r2 = j >> 3;
                    const int c4 = j & 7;
                    cp16(sring + st * TILE_B + j * 16,
                         gq + (size_t)(tn * ROWS + r2) * ROW_B + c4 * 16);
                }
            }
        }
        CP_COMMIT();

        if (++st == NS) st = 0;
    }
}

extern "C" void kernel_launch(void* const* d_in, const int* in_sizes, int n_in,
                              void* d_out, int out_size)
{
    const float* x   = (const float*)d_in[0];
    float*       out = (float*)d_out;
    inorm_kernel<<<512, 256>>>(x, out);
}

// round 11
// speedup vs baseline: 1.1283x; 1.1175x over previous
#include <cuda_runtime.h>
#include <cstdint>

// x: (8,16,2000,128) fp32. Per (b,c,f) column: POOL=10 block sums, causal
// cumulative mean/var over pooled blocks, normalize. Single pass.
//
// Grid = 1024 CTAs: (b*C+c) x (f-group QF=16) — the bench-fastest grid shape —
// with the register-consume + distributed-scan tile engine:
//   A: thread (b = tid>>4, f = tid&15) loads its 10 elements ONCE to regs,
//      writes block sums to bsArr.
//   B: distributed scan — each thread sums bsArr[0..b] + ping-pong carry in
//      registers (no dedicated scan warp/phase); b==7 threads publish carry.
//   C: normalize from registers, streaming STG (__stcs).
// 2 barriers/tile. Ring NS=5 x 5120 B (26.9 KB smem -> 8 CTAs/SM, ~28 w/SM).

#define TT      2000
#define FF      128
#define PP      10
#define TT1     200
#define TB      8                    // pooled blocks per tile
#define NT      25                   // tiles
#define NS      5                    // ring stages
#define QF      16                   // f-columns per CTA
#define ROWS    (TB * PP)            // 80 rows per tile
#define TILE_F  (ROWS * QF)          // 1280 floats
#define TILE_B  (TILE_F * 4)         // 5120 B
#define SLOTS4  (TILE_F / 4)         // 320 float4 slots
#define ROW_B   (FF * 4)             // 512 B global row stride
#define EPSV    1e-5f

__device__ __forceinline__ uint32_t s2u32(const void* p) {
    uint32_t a;
    asm("{ .reg .u64 t; cvta.to.shared.u64 t, %1; cvt.u32.u64 %0, t; }"
        : "=r"(a) : "l"(p));
    return a;
}
__device__ __forceinline__ void cp16(uint32_t saddr, const void* gaddr) {
    asm volatile("cp.async.cg.shared.global [%0], [%1], 16;\n"
                 :: "r"(saddr), "l"(gaddr));
}
#define CP_COMMIT() asm volatile("cp.async.commit_group;\n")
#define CP_WAIT(n)  asm volatile("cp.async.wait_group %0;\n" :: "n"(n))

__global__ void __launch_bounds__(128)
inorm_kernel(const float* __restrict__ x, float* __restrict__ out)
{
    __shared__ float  ring[NS * TILE_F];        // 25600 B
    __shared__ float2 bsArr[TB * QF];           //  1024 B
    __shared__ float2 carry[2][QF];             //   256 B

    const int col = blockIdx.x >> 3;            // 0..127
    const int q   = blockIdx.x & 7;             // f-group of 16
    const int tid = threadIdx.x;
    const int b   = tid >> 4;                   // block within tile, 0..7
    const int f   = tid & 15;                   // f within group

    const char* gq = (const char*)(x   + (size_t)col * (TT * FF) + q * QF);
    char*       oq = (char*)(out + (size_t)col * (TT * FF) + q * QF);

    const uint32_t sring = s2u32(ring);

    if (tid < QF)                                // zero carry slot 0
        carry[0][tid] = make_float2(0.f, 0.f);

    // Prologue: fill ring with tiles 0..NS-1 (one commit group per stage)
    #pragma unroll
    for (int st = 0; st < NS; st++) {
        #pragma unroll
        for (int i = 0; i < 3; i++) {
            const int j = tid + 128 * i;        // float4 slot 0..383 (guard 320)
            if (j < SLOTS4) {
                const int r  = j >> 2;          // row 0..79
                const int c4 = j & 3;           // float4 within 64B row seg
                cp16(sring + st * TILE_B + j * 16,
                     gq + (size_t)(st * ROWS + r) * ROW_B + c4 * 16);
            }
        }
        CP_COMMIT();
    }

    int st = 0;

    #pragma unroll 1
    for (int t = 0; t < NT; t++) {
        CP_WAIT(NS - 1);
        __syncthreads();          // stage st ready; carry[t&1] published;
                                  // previous tile's bsArr reads done

        const float* tile = ring + st * TILE_F;

        // ── A: load my (b,f) block once into registers; exchange block sums
        float a[PP];
        {
            const float* rp = tile + b * (PP * QF) + f;
            #pragma unroll
            for (int i = 0; i < PP; i++) a[i] = rp[i * QF];
        }
        float bs = 0.f, bs2 = 0.f;
        #pragma unroll
        for (int i = 0; i < PP; i++) { bs += a[i]; bs2 = fmaf(a[i], a[i], bs2); }
        bsArr[b * QF + f] = make_float2(bs, bs2);
        __syncthreads();          // bsArr ready; stage st consumed to regs

        // ── B: distributed scan. thread (b,f) sums bsArr[0..b] + carry.
        float sA, s2A;
        {
            const float2 c0 = carry[t & 1][f];
            sA = c0.x; s2A = c0.y;
            #pragma unroll
            for (int j = 0; j < TB; j++) {
                if (j <= b) {                  // predicated, max 8 LDS.64
                    const float2 v = bsArr[j * QF + f];
                    sA += v.x; s2A += v.y;
                }
            }
            if (b == TB - 1)                   // b==7 threads publish carry
                carry[(t + 1) & 1][f] = make_float2(sA, s2A);
        }
        const float invn = __fdividef(1.0f, (float)((t * TB + b + 1) * PP));
        const float m    = sA * invn;
        const float var  = fmaf(-m, m, s2A * invn);
        const float r    = rsqrtf(var + EPSV);

        // ── C: normalize from registers, streaming stores
        {
            char* og = oq + (size_t)(t * ROWS + b * PP) * ROW_B + f * 4;
            #pragma unroll
            for (int i = 0; i < PP; i++)
                __stcs((float*)(og + (size_t)i * ROW_B), (a[i] - m) * r);
        }

        // ── refill stage st with tile t+NS (all warps; always commit)
        const int tn = t + NS;
        if (tn < NT) {
            #pragma unroll
            for (int i = 0; i < 3; i++) {
                const int j = tid + 128 * i;
                if (j < SLOTS4) {
                    const int r2 = j >> 2;
                    const int c4 = j & 3;
                    cp16(sring + st * TILE_B + j * 16,
                         gq + (size_t)(tn * ROWS + r2) * ROW_B + c4 * 16);
                }
            }
        }
        CP_COMMIT();

        if (++st == NS) st = 0;
    }
}

extern "C" void kernel_launch(void* const* d_in, const int* in_sizes, int n_in,
                              void* d_out, int out_size)
{
    const float* x   = (const float*)d_in[0];
    float*       out = (float*)d_out;
    inorm_kernel<<<1024, 128>>>(x, out);
}